// round 1
// baseline (speedup 1.0000x reference)
#include <cuda_runtime.h>
#include <cstddef>

#define BB 64
#define TT 1024
#define II 512
#define HH 512
#define G4 2048

// ---------------- scratch (static device globals: allocation-free rule) ----
__device__ float g_xg[(size_t)BB * TT * G4];   // 512 MB precomputed input gates
__device__ float g_h[2][BB][HH];               // ping-pong hidden state
__device__ unsigned g_count;
__device__ unsigned g_gen;

using u64 = unsigned long long;

// ---------------- f32x2 helpers (FFMA2 only reachable via PTX) -------------
__device__ __forceinline__ void fma2(u64& d, u64 a, u64 b) {
    asm volatile("fma.rn.f32x2 %0, %1, %2, %3;" : "=l"(d) : "l"(a), "l"(b), "l"(d));
}
__device__ __forceinline__ u64 pack2(float lo, float hi) {
    u64 r; asm("mov.b64 %0, {%1, %2};" : "=l"(r) : "f"(lo), "f"(hi)); return r;
}
__device__ __forceinline__ float hsum2(u64 v) {
    float lo, hi;
    asm("mov.b64 {%0, %1}, %2;" : "=f"(lo), "=f"(hi) : "l"(v));
    return lo + hi;
}
__device__ __forceinline__ float sigmoidf(float x) {
    return 1.0f / (1.0f + __expf(-x));
}

// ---------------- init (reset barrier state each launch; graph-safe) -------
__global__ void init_kernel() {
    g_count = 0u;
    g_gen = 0u;
}

// ============================================================================
// Phase 1: xg[m,n] = x[m,:] . W_ih[n,:] + (b_ih[n] + b_hh[n])
// m = b*T + t in [0, 65536), n in [0, 2048), K = 512.
// 128x128 tile, BK=16, 256 threads, 8x8 micro-tile, f32x2 packed over n-pairs.
// A duplicated in SMEM ({a,a} pairs) so no pack instructions in the hot loop.
// ============================================================================
#define BK 16
#define ASTRIDE 260   // 2*128 + 4 pad (rows land on distinct banks, 16B aligned)
#define BSTRIDE 260   // 128 + pad (same properties)

__global__ __launch_bounds__(256, 2) void lstm_gemm1(
    const float* __restrict__ x, const float* __restrict__ Wih,
    const float* __restrict__ bih, const float* __restrict__ bhh)
{
    __shared__ float As[BK][ASTRIDE];  // [k][2*m] duplicated A values
    __shared__ float Bs[BK][BSTRIDE];  // [k][n]

    const int tid = threadIdx.x;
    const int tx = tid & 15;   // n-group: cols tx*4..+3 and 64+tx*4..+3
    const int ty = tid >> 4;   // m-group: rows ty*4..+3 and 64+ty*4..+3
    const int mtile = blockIdx.y;
    const int ntile = blockIdx.x;

    u64 acc[2][4][2][2];       // [mhalf][mi][nhalf][npair]
#pragma unroll
    for (int a = 0; a < 2; a++)
#pragma unroll
        for (int b = 0; b < 4; b++)
#pragma unroll
            for (int c = 0; c < 2; c++)
#pragma unroll
                for (int d = 0; d < 2; d++)
                    acc[a][b][c][d] = 0ull;

    // biases for this thread's 8 n columns
    float bias[2][4];
#pragma unroll
    for (int nh = 0; nh < 2; nh++)
#pragma unroll
        for (int i = 0; i < 4; i++) {
            int n = ntile * 128 + nh * 64 + tx * 4 + i;
            bias[nh][i] = bih[n] + bhh[n];
        }

    const size_t mbase = (size_t)mtile * 128;
    const size_t nbase = (size_t)ntile * 128;

    for (int kc = 0; kc < II / BK; kc++) {
        // ---- stage A (duplicated) and B (transposed) ----
#pragma unroll
        for (int r = 0; r < 2; r++) {
            int id = tid + r * 256;          // 512 ids: 128 m-rows x 4 kq
            int m = id >> 2, kq = id & 3;
            float4 va = *(const float4*)&x[(mbase + m) * II + kc * BK + kq * 4];
            *(u64*)&As[kq * 4 + 0][2 * m] = pack2(va.x, va.x);
            *(u64*)&As[kq * 4 + 1][2 * m] = pack2(va.y, va.y);
            *(u64*)&As[kq * 4 + 2][2 * m] = pack2(va.z, va.z);
            *(u64*)&As[kq * 4 + 3][2 * m] = pack2(va.w, va.w);
            float4 vb = *(const float4*)&Wih[(nbase + m) * II + kc * BK + kq * 4];
            Bs[kq * 4 + 0][m] = vb.x;
            Bs[kq * 4 + 1][m] = vb.y;
            Bs[kq * 4 + 2][m] = vb.z;
            Bs[kq * 4 + 3][m] = vb.w;
        }
        __syncthreads();

        // ---- compute ----
#pragma unroll
        for (int k = 0; k < BK; k++) {
            u64 Am[2][4];
            ulonglong2 t0 = *(const ulonglong2*)&As[k][8 * ty];
            ulonglong2 t1 = *(const ulonglong2*)&As[k][8 * ty + 4];
            ulonglong2 t2 = *(const ulonglong2*)&As[k][128 + 8 * ty];
            ulonglong2 t3 = *(const ulonglong2*)&As[k][128 + 8 * ty + 4];
            Am[0][0] = t0.x; Am[0][1] = t0.y; Am[0][2] = t1.x; Am[0][3] = t1.y;
            Am[1][0] = t2.x; Am[1][1] = t2.y; Am[1][2] = t3.x; Am[1][3] = t3.y;
            u64 Bp[2][2];
            ulonglong2 u0 = *(const ulonglong2*)&Bs[k][4 * tx];
            ulonglong2 u1 = *(const ulonglong2*)&Bs[k][64 + 4 * tx];
            Bp[0][0] = u0.x; Bp[0][1] = u0.y;
            Bp[1][0] = u1.x; Bp[1][1] = u1.y;
#pragma unroll
            for (int mh = 0; mh < 2; mh++)
#pragma unroll
                for (int mi = 0; mi < 4; mi++)
#pragma unroll
                    for (int nh = 0; nh < 2; nh++)
#pragma unroll
                        for (int np = 0; np < 2; np++)
                            fma2(acc[mh][mi][nh][np], Am[mh][mi], Bp[nh][np]);
        }
        __syncthreads();
    }

    // ---- epilogue: add bias, store float4 ----
#pragma unroll
    for (int mh = 0; mh < 2; mh++)
#pragma unroll
        for (int mi = 0; mi < 4; mi++) {
            size_t m = mbase + mh * 64 + ty * 4 + mi;
#pragma unroll
            for (int nh = 0; nh < 2; nh++) {
                size_t n0 = nbase + nh * 64 + tx * 4;
                float4 o;
                float lo, hi;
                lo = hsum2(0); (void)lo; (void)hi; // no-op, keeps compiler calm
                {
                    u64 v = acc[mh][mi][nh][0];
                    float a, b2;
                    asm("mov.b64 {%0, %1}, %2;" : "=f"(a), "=f"(b2) : "l"(v));
                    o.x = a + bias[nh][0];
                    o.y = b2 + bias[nh][1];
                }
                {
                    u64 v = acc[mh][mi][nh][1];
                    float a, b2;
                    asm("mov.b64 {%0, %1}, %2;" : "=f"(a), "=f"(b2) : "l"(v));
                    o.z = a + bias[nh][2];
                    o.w = b2 + bias[nh][3];
                }
                *(float4*)&g_xg[m * G4 + n0] = o;
            }
        }
}

// ============================================================================
// Phase 2: persistent recurrent kernel. 128 CTAs x 256 threads.
// CTA owns 4 h-columns; thread owns (b = tid>>2, j = tid&3) and its 4 gates.
// W_hh slice (16 rows x 512) lives in SMEM for the whole kernel.
// Grid-wide barrier per timestep via atomics (all 128 CTAs wave-1 resident).
// ============================================================================
__device__ __forceinline__ void grid_sync(unsigned* gen) {
    __syncthreads();
    if (threadIdx.x == 0) {
        __threadfence();
        unsigned target = *gen + 1u;
        if (atomicAdd(&g_count, 1u) == gridDim.x - 1) {
            atomicExch(&g_count, 0u);
            __threadfence();
            atomicAdd(&g_gen, 1u);
        } else {
            while (*((volatile unsigned*)&g_gen) < target) { __nanosleep(32); }
        }
        __threadfence();
    }
    __syncthreads();
    *gen += 1u;
}

#define WSTRIDE 520   // 512 + 8 pad: 4 j-rows land on distinct banks, 16B-aligned

__global__ __launch_bounds__(256, 1) void lstm_rec(
    const float* __restrict__ Whh, float* __restrict__ out)
{
    __shared__ float Ws[16][WSTRIDE];  // rows: g*4 + j

    const int tid = threadIdx.x;
    const int j = tid & 3;
    const int b = tid >> 2;
    const int jg = blockIdx.x * 4 + j;

    // Load this CTA's 16 W_hh rows (gate g, local col jj) into SMEM
    for (int idx = tid; idx < 16 * 128; idx += 256) {
        int r = idx >> 7, kq = idx & 127;
        int g = r >> 2, jj = r & 3;
        float4 v = *(const float4*)&Whh[((size_t)g * HH + blockIdx.x * 4 + jj) * HH + kq * 4];
        *(float4*)&Ws[r][kq * 4] = v;
    }
    __syncthreads();

    unsigned gen = 0;
    const float* xgp = g_xg + (size_t)b * TT * G4 + jg;

    // ---- t = 0: h_prev = 0, c_prev = 0 ----
    float c, h;
    {
        float x0 = xgp[0], x1 = xgp[512], x2 = xgp[1024], x3 = xgp[1536];
        float iv = sigmoidf(x0);
        float gv = tanhf(x2);
        float ov = sigmoidf(x3);
        (void)x1; // f * c_prev = 0
        c = iv * gv;
        h = ov * tanhf(c);
        g_h[1][b][jg] = h;
    }
    grid_sync(&gen);

    int cur = 1;
    for (int t = 1; t < TT; t++) {
        const float* xp = xgp + (size_t)t * G4;
        float x0 = __ldg(xp);
        float x1 = __ldg(xp + 512);
        float x2 = __ldg(xp + 1024);
        float x3 = __ldg(xp + 1536);

        const ulonglong2* __restrict__ hp = (const ulonglong2*)&g_h[cur][b][0];
        const ulonglong2* __restrict__ w0 = (const ulonglong2*)&Ws[0 + j][0];
        const ulonglong2* __restrict__ w1 = (const ulonglong2*)&Ws[4 + j][0];
        const ulonglong2* __restrict__ w2 = (const ulonglong2*)&Ws[8 + j][0];
        const ulonglong2* __restrict__ w3 = (const ulonglong2*)&Ws[12 + j][0];

        u64 a0 = 0, a1 = 0, a2 = 0, a3 = 0;
        u64 e0 = 0, e1 = 0, e2 = 0, e3 = 0;
#pragma unroll 8
        for (int q = 0; q < 128; q++) {
            ulonglong2 hv = hp[q];
            ulonglong2 wv;
            wv = w0[q]; fma2(a0, wv.x, hv.x); fma2(e0, wv.y, hv.y);
            wv = w1[q]; fma2(a1, wv.x, hv.x); fma2(e1, wv.y, hv.y);
            wv = w2[q]; fma2(a2, wv.x, hv.x); fma2(e2, wv.y, hv.y);
            wv = w3[q]; fma2(a3, wv.x, hv.x); fma2(e3, wv.y, hv.y);
        }

        float gi = x0 + hsum2(a0) + hsum2(e0);
        float gf = x1 + hsum2(a1) + hsum2(e1);
        float gg = x2 + hsum2(a2) + hsum2(e2);
        float go = x3 + hsum2(a3) + hsum2(e3);

        float iv = sigmoidf(gi);
        float fv = sigmoidf(gf);
        float gv = tanhf(gg);
        float ov = sigmoidf(go);
        c = fv * c + iv * gv;
        h = ov * tanhf(c);

        if (t == TT - 1) {
            out[(size_t)b * HH + jg] = h;   // final hidden state
        } else {
            g_h[cur ^ 1][b][jg] = h;
            grid_sync(&gen);
        }
        cur ^= 1;
    }
}

// ============================================================================
extern "C" void kernel_launch(void* const* d_in, const int* in_sizes, int n_in,
                              void* d_out, int out_size) {
    const float* x   = (const float*)d_in[0];
    const float* Wih = (const float*)d_in[1];
    const float* Whh = (const float*)d_in[2];
    const float* bih = (const float*)d_in[3];
    const float* bhh = (const float*)d_in[4];
    float* out = (float*)d_out;

    init_kernel<<<1, 1>>>();
    lstm_gemm1<<<dim3(G4 / 128, (BB * TT) / 128), 256>>>(x, Wih, bih, bhh);
    lstm_rec<<<HH / 4, 256>>>(Whh, out);
}

// round 6
// speedup vs baseline: 1.0539x; 1.0539x over previous
#include <cuda_runtime.h>
#include <cstddef>

#define BB 64
#define TT 1024
#define II 512
#define HH 512
#define G4 2048

// ---------------- scratch (static device globals: allocation-free rule) ----
__device__ float g_xg[(size_t)BB * TT * G4];   // 512 MB precomputed input gates
__device__ float g_h[2][BB][HH];               // ping-pong hidden state
__device__ unsigned g_flag[128 * 32];          // per-CTA flags, 128B apart

using u64 = unsigned long long;

// ---------------- f32x2 helpers (FFMA2 only reachable via PTX) -------------
__device__ __forceinline__ void fma2(u64& d, u64 a, u64 b) {
    asm("fma.rn.f32x2 %0, %1, %2, %3;" : "=l"(d) : "l"(a), "l"(b), "l"(d));
}
__device__ __forceinline__ u64 pack2(float lo, float hi) {
    u64 r; asm("mov.b64 %0, {%1, %2};" : "=l"(r) : "f"(lo), "f"(hi)); return r;
}
__device__ __forceinline__ float hsum2(u64 v) {
    float lo, hi;
    asm("mov.b64 {%0, %1}, %2;" : "=f"(lo), "=f"(hi) : "l"(v));
    return lo + hi;
}
__device__ __forceinline__ float sigmoidf(float x) {
    return 1.0f / (1.0f + __expf(-x));
}

// ---------------- release/acquire flag ops + L2-only vector load -----------
__device__ __forceinline__ unsigned ld_acquire_u32(const unsigned* p) {
    unsigned v;
    asm volatile("ld.acquire.gpu.global.b32 %0, [%1];" : "=r"(v) : "l"(p) : "memory");
    return v;
}
__device__ __forceinline__ void st_release_u32(unsigned* p, unsigned v) {
    asm volatile("fence.acq_rel.gpu;" ::: "memory");
    asm volatile("st.relaxed.gpu.global.b32 [%0], %1;" :: "l"(p), "r"(v) : "memory");
}
// L2-only load (bypasses non-coherent L1 — h ping-pong buffers would otherwise
// be read from 2-step-stale L1 lines; L1D is only flushed per kernel launch).
__device__ __forceinline__ ulonglong2 ldcg_u64x2(const ulonglong2* p) {
    ulonglong2 v;
    asm("ld.global.cg.v2.u64 {%0, %1}, [%2];" : "=l"(v.x), "=l"(v.y) : "l"(p));
    return v;
}

// ============================================================================
// Phase 1: xg[m,n] = x[m,:] . W_ih[n,:] + (b_ih[n] + b_hh[n])
// m = b*T + t in [0, 65536), n in [0, 2048), K = 512.
// 128x128 tile, BK=16, 256 threads, 8x8 micro-tile, f32x2 packed over n-pairs.
// A duplicated in SMEM ({a,a} pairs) so no pack instructions in the hot loop.
// Block (0,0) also resets the phase-2 flags (stream order guarantees
// visibility before lstm_rec starts).
// ============================================================================
#define BK 16
#define ASTRIDE 260   // 2*128 + 4 pad (rows land on distinct banks, 16B aligned)
#define BSTRIDE 260   // 128 + pad (same properties)

__global__ __launch_bounds__(256, 2) void lstm_gemm1(
    const float* __restrict__ x, const float* __restrict__ Wih,
    const float* __restrict__ bih, const float* __restrict__ bhh)
{
    __shared__ float As[BK][ASTRIDE];  // [k][2*m] duplicated A values
    __shared__ float Bs[BK][BSTRIDE];  // [k][n]

    const int tid = threadIdx.x;

    // reset recurrent-phase flags (lstm_rec starts only after this grid ends)
    if (blockIdx.x == 0 && blockIdx.y == 0 && tid < 128) g_flag[tid * 32] = 0u;

    const int tx = tid & 15;   // n-group: cols tx*4..+3 and 64+tx*4..+3
    const int ty = tid >> 4;   // m-group: rows ty*4..+3 and 64+ty*4..+3
    const int mtile = blockIdx.y;
    const int ntile = blockIdx.x;

    u64 acc[2][4][2][2];       // [mhalf][mi][nhalf][npair]
#pragma unroll
    for (int a = 0; a < 2; a++)
#pragma unroll
        for (int b = 0; b < 4; b++)
#pragma unroll
            for (int c = 0; c < 2; c++)
#pragma unroll
                for (int d = 0; d < 2; d++)
                    acc[a][b][c][d] = 0ull;

    // biases for this thread's 8 n columns
    float bias[2][4];
#pragma unroll
    for (int nh = 0; nh < 2; nh++)
#pragma unroll
        for (int i = 0; i < 4; i++) {
            int n = ntile * 128 + nh * 64 + tx * 4 + i;
            bias[nh][i] = bih[n] + bhh[n];
        }

    const size_t mbase = (size_t)mtile * 128;
    const size_t nbase = (size_t)ntile * 128;

    for (int kc = 0; kc < II / BK; kc++) {
        // ---- stage A (duplicated) and B (transposed) ----
#pragma unroll
        for (int r = 0; r < 2; r++) {
            int id = tid + r * 256;          // 512 ids: 128 m-rows x 4 kq
            int m = id >> 2, kq = id & 3;
            float4 va = *(const float4*)&x[(mbase + m) * II + kc * BK + kq * 4];
            *(u64*)&As[kq * 4 + 0][2 * m] = pack2(va.x, va.x);
            *(u64*)&As[kq * 4 + 1][2 * m] = pack2(va.y, va.y);
            *(u64*)&As[kq * 4 + 2][2 * m] = pack2(va.z, va.z);
            *(u64*)&As[kq * 4 + 3][2 * m] = pack2(va.w, va.w);
            float4 vb = *(const float4*)&Wih[(nbase + m) * II + kc * BK + kq * 4];
            Bs[kq * 4 + 0][m] = vb.x;
            Bs[kq * 4 + 1][m] = vb.y;
            Bs[kq * 4 + 2][m] = vb.z;
            Bs[kq * 4 + 3][m] = vb.w;
        }
        __syncthreads();

        // ---- compute ----
#pragma unroll
        for (int k = 0; k < BK; k++) {
            u64 Am[2][4];
            ulonglong2 t0 = *(const ulonglong2*)&As[k][8 * ty];
            ulonglong2 t1 = *(const ulonglong2*)&As[k][8 * ty + 4];
            ulonglong2 t2 = *(const ulonglong2*)&As[k][128 + 8 * ty];
            ulonglong2 t3 = *(const ulonglong2*)&As[k][128 + 8 * ty + 4];
            Am[0][0] = t0.x; Am[0][1] = t0.y; Am[0][2] = t1.x; Am[0][3] = t1.y;
            Am[1][0] = t2.x; Am[1][1] = t2.y; Am[1][2] = t3.x; Am[1][3] = t3.y;
            u64 Bp[2][2];
            ulonglong2 u0 = *(const ulonglong2*)&Bs[k][4 * tx];
            ulonglong2 u1 = *(const ulonglong2*)&Bs[k][64 + 4 * tx];
            Bp[0][0] = u0.x; Bp[0][1] = u0.y;
            Bp[1][0] = u1.x; Bp[1][1] = u1.y;
#pragma unroll
            for (int mh = 0; mh < 2; mh++)
#pragma unroll
                for (int mi = 0; mi < 4; mi++)
#pragma unroll
                    for (int nh = 0; nh < 2; nh++)
#pragma unroll
                        for (int np = 0; np < 2; np++)
                            fma2(acc[mh][mi][nh][np], Am[mh][mi], Bp[nh][np]);
        }
        __syncthreads();
    }

    // ---- epilogue: add bias, store float4 ----
#pragma unroll
    for (int mh = 0; mh < 2; mh++)
#pragma unroll
        for (int mi = 0; mi < 4; mi++) {
            size_t m = mbase + mh * 64 + ty * 4 + mi;
#pragma unroll
            for (int nh = 0; nh < 2; nh++) {
                size_t n0 = nbase + nh * 64 + tx * 4;
                float4 o;
                {
                    float a, b2;
                    asm("mov.b64 {%0, %1}, %2;" : "=f"(a), "=f"(b2)
                        : "l"(acc[mh][mi][nh][0]));
                    o.x = a + bias[nh][0];
                    o.y = b2 + bias[nh][1];
                }
                {
                    float a, b2;
                    asm("mov.b64 {%0, %1}, %2;" : "=f"(a), "=f"(b2)
                        : "l"(acc[mh][mi][nh][1]));
                    o.z = a + bias[nh][2];
                    o.w = b2 + bias[nh][3];
                }
                *(float4*)&g_xg[m * G4 + n0] = o;
            }
        }
}

// ============================================================================
// Phase 2: persistent recurrent kernel. 128 CTAs x 256 threads.
// CTA owns 4 h-columns; thread owns (b = tid>>2, j = tid&3) and its 4 gates.
// W_hh slice (16 rows x 512) lives in SMEM for the whole kernel.
//
// Cross-CTA sync per timestep via distributed flags:
//   producer: write h slice -> __syncthreads -> thread0 fence+st flag = t+1
//   consumer: threads 0..127 acquire-poll flag[i] >= t -> __syncthreads ->
//             read h via ld.global.cg (L2-only; L1 lines would be stale)
// No central atomic counter, no nanosleep, no L1-flushing membar in the loop.
// Buffer-reuse safety: flag[i] = t means CTA i finished all step-(t-1) reads
// before publishing h(t-1), so writing buffer t&1 at step t is safe.
//
// LDS bank audit: the 4 Ws rows a warp reads per iter sit WSTRIDE=520 floats
// apart -> bank offsets {0,8,16,24}; each 16B chunk spans 4 banks; 8-lane
// broadcast per address -> conflict-free, ~1-2 cyc per LDS.128.
// ============================================================================
#define WSTRIDE 520   // 512 + 8 pad: 4 j-rows land on distinct banks, 16B-aligned

__global__ __launch_bounds__(256, 1) void lstm_rec(
    const float* __restrict__ Whh, float* __restrict__ out)
{
    __shared__ float Ws[16][WSTRIDE];  // rows: g*4 + j

    const int tid = threadIdx.x;
    const int j = tid & 3;
    const int b = tid >> 2;
    const int jg = blockIdx.x * 4 + j;

    // Load this CTA's 16 W_hh rows (gate g, local col jj) into SMEM
    for (int idx = tid; idx < 16 * 128; idx += 256) {
        int r = idx >> 7, kq = idx & 127;
        int g = r >> 2, jj = r & 3;
        float4 v = *(const float4*)&Whh[((size_t)g * HH + blockIdx.x * 4 + jj) * HH + kq * 4];
        *(float4*)&Ws[r][kq * 4] = v;
    }
    __syncthreads();

    const float* xgp = g_xg + (size_t)b * TT * G4 + jg;

    // ---- t = 0: h_prev = 0, c_prev = 0 ----
    float c, h;
    {
        float x0 = xgp[0], x2 = xgp[1024], x3 = xgp[1536];
        float iv = sigmoidf(x0);
        float gv = tanhf(x2);
        float ov = sigmoidf(x3);
        c = iv * gv;
        h = ov * tanhf(c);
        g_h[0][b][jg] = h;
    }
    __syncthreads();
    if (tid == 0) st_release_u32(&g_flag[blockIdx.x * 32], 1u);

    for (int t = 1; t < TT; t++) {
        // issue xg loads early (independent of the flag wait)
        const float* xp = xgp + (size_t)t * G4;
        float x0 = __ldg(xp);
        float x1 = __ldg(xp + 512);
        float x2 = __ldg(xp + 1024);
        float x3 = __ldg(xp + 1536);

        // wait for all CTAs to have published h(t-1)
        if (tid < 128) {
            while (ld_acquire_u32(&g_flag[tid * 32]) < (unsigned)t) { }
        }
        __syncthreads();

        const ulonglong2* __restrict__ hp = (const ulonglong2*)&g_h[(t - 1) & 1][b][0];
        const ulonglong2* __restrict__ w0 = (const ulonglong2*)&Ws[0 + j][0];
        const ulonglong2* __restrict__ w1 = (const ulonglong2*)&Ws[4 + j][0];
        const ulonglong2* __restrict__ w2 = (const ulonglong2*)&Ws[8 + j][0];
        const ulonglong2* __restrict__ w3 = (const ulonglong2*)&Ws[12 + j][0];

        u64 a0 = 0, a1 = 0, a2 = 0, a3 = 0;
        u64 e0 = 0, e1 = 0, e2 = 0, e3 = 0;
#pragma unroll 8
        for (int q = 0; q < 128; q++) {
            ulonglong2 hv = ldcg_u64x2(hp + q);
            ulonglong2 wv;
            wv = w0[q]; fma2(a0, wv.x, hv.x); fma2(e0, wv.y, hv.y);
            wv = w1[q]; fma2(a1, wv.x, hv.x); fma2(e1, wv.y, hv.y);
            wv = w2[q]; fma2(a2, wv.x, hv.x); fma2(e2, wv.y, hv.y);
            wv = w3[q]; fma2(a3, wv.x, hv.x); fma2(e3, wv.y, hv.y);
        }

        float gi = x0 + hsum2(a0) + hsum2(e0);
        float gf = x1 + hsum2(a1) + hsum2(e1);
        float gg = x2 + hsum2(a2) + hsum2(e2);
        float go = x3 + hsum2(a3) + hsum2(e3);

        float iv = sigmoidf(gi);
        float fv = sigmoidf(gf);
        float gv = tanhf(gg);
        float ov = sigmoidf(go);
        c = fv * c + iv * gv;
        h = ov * tanhf(c);

        if (t == TT - 1) {
            out[(size_t)b * HH + jg] = h;   // final hidden state
        } else {
            g_h[t & 1][b][jg] = h;
            __syncthreads();
            if (tid == 0) st_release_u32(&g_flag[blockIdx.x * 32], (unsigned)(t + 1));
        }
    }
}

// ============================================================================
extern "C" void kernel_launch(void* const* d_in, const int* in_sizes, int n_in,
                              void* d_out, int out_size) {
    const float* x   = (const float*)d_in[0];
    const float* Wih = (const float*)d_in[1];
    const float* Whh = (const float*)d_in[2];
    const float* bih = (const float*)d_in[3];
    const float* bhh = (const float*)d_in[4];
    float* out = (float*)d_out;

    lstm_gemm1<<<dim3(G4 / 128, (BB * TT) / 128), 256>>>(x, Wih, bih, bhh);
    lstm_rec<<<HH / 4, 256>>>(Whh, out);
}